// round 9
// baseline (speedup 1.0000x reference)
#include <cuda_runtime.h>
#include <cuda_bf16.h>
#include <cstdint>

// VectorQuantizer: bf16 mma.sync prefilter with SELF-CALIBRATING fragment
// mapping + exact-fp32 FFMA2 rescore. (tcgen05 unavailable on compute_103.)
//
// Frozen exact-dist contract (rel_err==0.0 in R2/R3):
//   Sx/Se: rounded squares, sequential sum. dot: 4 FFMA2 chains, add2 tree, lo+hi.
//   dist = fmaf(-2, dot, Sx+Se[k]); first-index argmin.
//
// Probe 1 discovers each output register's true (row,col) at runtime
// (A[r]=2^r, B[n]=2^(16n) => c = 2^(r+16n), decoded from the fp32 exponent).
// Probe 2 validates kstep pairing (scales 1,2,4,8 => only identity sums to 85).
// Any anomaly / empty list / overflow => exact full-scan fallback (always correct).

#define KC   512
#define DD   64
#define TENSOR_ELEMS 8388608
#define NCTAS 512            // 131072 px / 256
#define TPB   256
#define CAP   16

// smem layout (bytes)
#define OFF_A     0          // 256 rows x 128B bf16 (SW128)
#define OFF_CB    32768      // 512 rows x 128B bf16 (SW128)
#define OFF_SE    98304      // 512 f32
#define OFF_MARG  100352     // 256 f32
#define OFF_CNT   101376     // 256 i32
#define OFF_CAND  102400     // 256*CAP u16 = 8192 B
#define OFF_FLAG  110592     // 256 B
#define OFF_BAD   110848     // 4 B
#define OFF_RED   110880     // 8 f32
#define SMEM_TOTAL 110912

typedef unsigned long long u64v;

// ---------- packed fp32 helpers (frozen R2 formula) ----------
__device__ __forceinline__ u64v fma2(u64v a, u64v b, u64v c) {
    u64v d_; asm("fma.rn.f32x2 %0, %1, %2, %3;" : "=l"(d_) : "l"(a), "l"(b), "l"(c)); return d_;
}
__device__ __forceinline__ u64v add2(u64v a, u64v b) {
    u64v d_; asm("add.rn.f32x2 %0, %1, %2;" : "=l"(d_) : "l"(a), "l"(b)); return d_;
}
__device__ __forceinline__ u64v pack2(float lo, float hi) {
    u64v d_; asm("mov.b64 %0, {%1, %2};" : "=l"(d_) : "f"(lo), "f"(hi)); return d_;
}
__device__ __forceinline__ void unpack2(u64v v, float& lo, float& hi) {
    asm("mov.b64 {%0, %1}, %2;" : "=f"(lo), "=f"(hi) : "l"(v));
}

// ---------- mma / ldmatrix ----------
__device__ __forceinline__ void ldsm_x4(uint32_t addr, uint32_t& r0, uint32_t& r1,
                                        uint32_t& r2, uint32_t& r3) {
    asm volatile("ldmatrix.sync.aligned.m8n8.x4.shared.b16 {%0,%1,%2,%3}, [%4];"
                 : "=r"(r0), "=r"(r1), "=r"(r2), "=r"(r3) : "r"(addr));
}
__device__ __forceinline__ void mma_bf16(float* c,
                                         const uint32_t* a, uint32_t b0, uint32_t b1) {
    asm volatile("mma.sync.aligned.m16n8k16.row.col.f32.bf16.bf16.f32 "
                 "{%0,%1,%2,%3}, {%4,%5,%6,%7}, {%8,%9}, {%0,%1,%2,%3};"
                 : "+f"(c[0]), "+f"(c[1]), "+f"(c[2]), "+f"(c[3])
                 : "r"(a[0]), "r"(a[1]), "r"(a[2]), "r"(a[3]), "r"(b0), "r"(b1));
}
__device__ __forceinline__ uint32_t smem_u32(const void* p) {
    uint32_t a; asm("{ .reg .u64 t; cvta.to.shared.u64 t, %1; cvt.u32.u64 %0, t; }"
                    : "=r"(a) : "l"(p));
    return a;
}
static __device__ __forceinline__ uint32_t sw128(uint32_t off) {
    return off ^ ((off >> 3) & 0x70);
}

// ---------- device globals ----------
__device__ __nv_bfloat16 g_cb_bf16[KC * DD];
__device__ float g_se[KC];
__device__ float g_enorm_max;
__device__ float g_partials[NCTAS];

__global__ void vq_prep(const float* __restrict__ emb) {
    __shared__ float sm[KC];
    const int k = threadIdx.x;
    const float* r = emb + k * DD;
    float s = 0.f;
#pragma unroll
    for (int d = 0; d < DD; d++) {
        float v = r[d];
        float t = v * v;
        s = s + t;
        g_cb_bf16[k * DD + d] = __float2bfloat16(v);
    }
    g_se[k] = s;
    sm[k] = s;
    __syncthreads();
    for (int o = 256; o; o >>= 1) {
        if (k < o) sm[k] = fmaxf(sm[k], sm[k + o]);
        __syncthreads();
    }
    if (k == 0) g_enorm_max = sqrtf(sm[0]);
}

__device__ __forceinline__ float exact_dist(int k, const u64v* xp, float Sx,
                                            const float* __restrict__ emb, float sek) {
    const float4* er = (const float4*)(emb + (k << 6));
    u64v a0 = 0ull, a1 = 0ull, a2 = 0ull, a3 = 0ull;
#pragma unroll
    for (int j = 0; j < 8; j++) {
        float4 e0 = er[2 * j];
        float4 e1 = er[2 * j + 1];
        a0 = fma2(xp[4 * j + 0], pack2(e0.x, e0.y), a0);
        a1 = fma2(xp[4 * j + 1], pack2(e0.z, e0.w), a1);
        a2 = fma2(xp[4 * j + 2], pack2(e1.x, e1.y), a2);
        a3 = fma2(xp[4 * j + 3], pack2(e1.z, e1.w), a3);
    }
    u64v s2 = add2(add2(a0, a1), add2(a2, a3));
    float lo, hi; unpack2(s2, lo, hi);
    float dot = lo + hi;
    return fmaf(-2.f, dot, Sx + sek);
}

// decode 2^(r+16n): returns bad flag contribution
__device__ __forceinline__ int dec_pow2(float v, int& r, int& n) {
    uint32_t u = __float_as_uint(v);
    if (!(v > 0.f) || (u & 0x7FFFFFu)) return 1;
    int e = (int)(u >> 23) - 127;
    if (e < 0 || e > 127) return 1;
    r = e & 15;
    n = e >> 4;
    return (n > 7) ? 1 : 0;
}

__global__ void __launch_bounds__(TPB, 2)
vq_main(const float* __restrict__ lat, const float* __restrict__ emb, float* __restrict__ out) {
    extern __shared__ char smem[];
    const uint32_t sbase = smem_u32(smem);
    const int tid  = threadIdx.x;
    const int lane = tid & 31;
    const int warp = tid >> 5;

    float* se_sm   = (float*)(smem + OFF_SE);
    float* marg_sm = (float*)(smem + OFF_MARG);
    int*   cnt_sm  = (int*)(smem + OFF_CNT);
    unsigned short* cand_sm = (unsigned short*)(smem + OFF_CAND);
    unsigned char*  flag_sm = (unsigned char*)(smem + OFF_FLAG);
    int*   bad_sm  = (int*)(smem + OFF_BAD);
    float* red_sm  = (float*)(smem + OFF_RED);

    cnt_sm[tid] = 0;
    flag_sm[tid] = 0;
    if (tid == 0) *bad_sm = 0;

    // ldmatrix address helpers (same formulas used by probes AND main loop)
    const uint32_t axor = (uint32_t)(lane & 7) << 4;
    const int arow = warp * 32 + (lane & 15);
    // A address: tile T, kstep ks
#define A_ADDR(T, ks) (sbase + OFF_A + \
    (((uint32_t)(arow + (T) * 16) * 128u + (uint32_t)(ks) * 32u + (uint32_t)(lane >> 4) * 16u) ^ axor))
    const uint32_t baddr0 = sbase + OFF_CB
        + ((((uint32_t)(lane & 7) * 128u) + (uint32_t)(lane >> 3) * 16u) ^ axor);

    int bad = 0;
    int rA = 0, rB = 0, nc0 = 0, nc1 = 1, nc2 = 0, nc3 = 1;

    // ================= PROBE 1: (row, col) mapping =================
    {
        const uint4 z = make_uint4(0, 0, 0, 0);
        uint4 f = z; f.x = (uint32_t)((127 + (tid & 15)) << 7);  // bf16 2^(tid&15) at byte 0
#pragma unroll
        for (int j = 0; j < 8; j++)
            *(uint4*)(smem + OFF_A + sw128((uint32_t)tid * 128u + j * 16u)) = (j == 0) ? f : z;
        if (tid < 8) {
            uint4 fb = z; fb.x = (uint32_t)((127 + 16 * tid) << 7);  // bf16 2^(16n)
#pragma unroll
            for (int j = 0; j < 8; j++)
                *(uint4*)(smem + OFF_CB + sw128((uint32_t)tid * 128u + j * 16u)) = (j == 0) ? fb : z;
        }
    }
    __syncthreads();
    {
        uint32_t p[4], q[4], b00, b01, b10x, b11x;
        ldsm_x4(A_ADDR(0, 0), p[0], p[1], p[2], p[3]);
        ldsm_x4(A_ADDR(1, 0), q[0], q[1], q[2], q[3]);
        ldsm_x4(baddr0, b00, b01, b10x, b11x);
        float c[4] = {0.f, 0.f, 0.f, 0.f}, d[4] = {0.f, 0.f, 0.f, 0.f};
        mma_bf16(c, p, b00, b01);
        mma_bf16(d, q, b00, b01);
        int r0, r1, r2, r3;
        bad |= dec_pow2(c[0], r0, nc0);
        bad |= dec_pow2(c[1], r1, nc1);
        bad |= dec_pow2(c[2], r2, nc2);
        bad |= dec_pow2(c[3], r3, nc3);
        if (r0 != r1 || r2 != r3) bad = 1;
        rA = r0; rB = r2;
#pragma unroll
        for (int i = 0; i < 4; i++)
            if (__float_as_uint(d[i]) != __float_as_uint(c[i])) bad = 1;  // tile1 == tile0 mapping
    }
    __syncthreads();

    // ================= PROBE 2: kstep pairing =================
    {
        const uint4 z = make_uint4(0, 0, 0, 0);
#pragma unroll
        for (int j = 0; j < 8; j++) {
            uint4 w = z;
            if ((j & 1) == 0) w.x = (uint32_t)((127 + (j >> 1)) << 7);  // bf16 2^ks at byte ks*32
            *(uint4*)(smem + OFF_A + sw128((uint32_t)tid * 128u + j * 16u)) = w;
        }
        if (tid < 8) {
#pragma unroll
            for (int j = 0; j < 8; j++) {
                uint4 w = z;
                if ((j & 1) == 0) w.x = (uint32_t)((127 + (j >> 1)) << 7);
                *(uint4*)(smem + OFF_CB + sw128((uint32_t)tid * 128u + j * 16u)) = w;
            }
        }
    }
    __syncthreads();
    {
        uint32_t a0[4], a1[4], a2[4], a3[4], b00, b01, b10, b11, b20, b21, b30, b31;
        ldsm_x4(A_ADDR(0, 0), a0[0], a0[1], a0[2], a0[3]);
        ldsm_x4(A_ADDR(0, 1), a1[0], a1[1], a1[2], a1[3]);
        ldsm_x4(A_ADDR(0, 2), a2[0], a2[1], a2[2], a2[3]);
        ldsm_x4(A_ADDR(0, 3), a3[0], a3[1], a3[2], a3[3]);
        ldsm_x4(baddr0,      b00, b01, b10, b11);
        ldsm_x4(baddr0 + 64, b20, b21, b30, b31);
        float c[4] = {0.f, 0.f, 0.f, 0.f};
        mma_bf16(c, a0, b00, b01);
        mma_bf16(c, a1, b10, b11);
        mma_bf16(c, a2, b20, b21);
        mma_bf16(c, a3, b30, b31);
#pragma unroll
        for (int i = 0; i < 4; i++) if (c[i] != 85.0f) bad = 1;  // 1+4+16+64, identity pairing only
    }
    if (bad) *bad_sm = 1;
    __syncthreads();

    // ================= stage real data =================
    const int P    = blockIdx.x * TPB + tid;
    const int base = ((P >> 12) << 18) + (P & 4095);
    {
        float Sx = 0.f;
        uint32_t xb[32];
#pragma unroll
        for (int i = 0; i < 32; i++) {
            float a = lat[base + ((2 * i) << 12)];
            float c = lat[base + ((2 * i + 1) << 12)];
            float ta = a * a, tc = c * c;
            Sx = Sx + ta; Sx = Sx + tc;
            __nv_bfloat162 h = __floats2bfloat162_rn(a, c);
            xb[i] = *(uint32_t*)&h;
        }
#pragma unroll
        for (int j = 0; j < 8; j++)
            *(uint4*)(smem + OFF_A + sw128((uint32_t)tid * 128u + j * 16u)) =
                make_uint4(xb[4 * j], xb[4 * j + 1], xb[4 * j + 2], xb[4 * j + 3]);
        marg_sm[tid] = 0.03125f * sqrtf(Sx) * 1.001f * g_enorm_max + 1e-4f;
    }
    {
        const uint4* cbg = (const uint4*)g_cb_bf16;
        for (int c = tid; c < 4096; c += TPB)
            *(uint4*)(smem + OFF_CB + sw128((uint32_t)c * 16u)) = cbg[c];
        for (int k = tid; k < KC; k += TPB) se_sm[k] = g_se[k];
    }
    __syncthreads();

    // ---- A fragments for real data ----
    uint32_t afr[2][4][4];
#pragma unroll
    for (int T = 0; T < 2; T++)
#pragma unroll
        for (int ks = 0; ks < 4; ks++)
            ldsm_x4(A_ADDR(T, ks), afr[T][ks][0], afr[T][ks][1], afr[T][ks][2], afr[T][ks][3]);

    // measured pixel routing
    const int pxA   = warp * 32 + rA;
    const int pxB   = warp * 32 + rB;
    const int pxA16 = pxA + 16;
    const int pxB16 = pxB + 16;

#define MMA_TILE(c, d, b00, b01, b10, b11, b20, b21, b30, b31) \
    mma_bf16(c, afr[0][0], b00, b01); mma_bf16(c, afr[0][1], b10, b11);  \
    mma_bf16(c, afr[0][2], b20, b21); mma_bf16(c, afr[0][3], b30, b31);  \
    mma_bf16(d, afr[1][0], b00, b01); mma_bf16(d, afr[1][1], b10, b11);  \
    mma_bf16(d, afr[1][2], b20, b21); mma_bf16(d, afr[1][3], b30, b31)

    // ---- pass 1: lane-local min approx score per pixel slot ----
    float tA = 3.4e38f, tB = 3.4e38f, tA16 = 3.4e38f, tB16 = 3.4e38f;
    {
        uint32_t baddr = baddr0;
        for (int nt = 0; nt < 64; nt++) {
            uint32_t b00, b01, b10, b11, b20, b21, b30, b31;
            ldsm_x4(baddr,      b00, b01, b10, b11);
            ldsm_x4(baddr + 64, b20, b21, b30, b31);
            baddr += 1024;
            float c[4] = {0.f, 0.f, 0.f, 0.f}, d[4] = {0.f, 0.f, 0.f, 0.f};
            MMA_TILE(c, d, b00, b01, b10, b11, b20, b21, b30, b31);
            const int k0 = nt * 8;
            float s0 = se_sm[k0 + nc0], s1 = se_sm[k0 + nc1];
            float s2 = se_sm[k0 + nc2], s3 = se_sm[k0 + nc3];
            tA   = fminf(tA,   fminf(fmaf(-2.f, c[0], s0), fmaf(-2.f, c[1], s1)));
            tB   = fminf(tB,   fminf(fmaf(-2.f, c[2], s2), fmaf(-2.f, c[3], s3)));
            tA16 = fminf(tA16, fminf(fmaf(-2.f, d[0], s0), fmaf(-2.f, d[1], s1)));
            tB16 = fminf(tB16, fminf(fmaf(-2.f, d[2], s2), fmaf(-2.f, d[3], s3)));
        }
    }
    tA   += marg_sm[pxA];
    tB   += marg_sm[pxB];
    tA16 += marg_sm[pxA16];
    tB16 += marg_sm[pxB16];

    // ---- pass 2: emit candidates (atomic per-pixel lists) ----
#define EMIT(score, thr, px, kk)                                          \
    do {                                                                  \
        if ((score) <= (thr)) {                                           \
            int _i = atomicAdd(&cnt_sm[px], 1);                           \
            if (_i < CAP) cand_sm[(px) * CAP + _i] = (unsigned short)(kk); \
            else flag_sm[px] = 1;                                         \
        }                                                                 \
    } while (0)
    {
        uint32_t baddr = baddr0;
        for (int nt = 0; nt < 64; nt++) {
            uint32_t b00, b01, b10, b11, b20, b21, b30, b31;
            ldsm_x4(baddr,      b00, b01, b10, b11);
            ldsm_x4(baddr + 64, b20, b21, b30, b31);
            baddr += 1024;
            float c[4] = {0.f, 0.f, 0.f, 0.f}, d[4] = {0.f, 0.f, 0.f, 0.f};
            MMA_TILE(c, d, b00, b01, b10, b11, b20, b21, b30, b31);
            const int k0 = nt * 8;
            float s0 = se_sm[k0 + nc0], s1 = se_sm[k0 + nc1];
            float s2 = se_sm[k0 + nc2], s3 = se_sm[k0 + nc3];
            EMIT(fmaf(-2.f, c[0], s0), tA,   pxA,   k0 + nc0);
            EMIT(fmaf(-2.f, c[1], s1), tA,   pxA,   k0 + nc1);
            EMIT(fmaf(-2.f, c[2], s2), tB,   pxB,   k0 + nc2);
            EMIT(fmaf(-2.f, c[3], s3), tB,   pxB,   k0 + nc3);
            EMIT(fmaf(-2.f, d[0], s0), tA16, pxA16, k0 + nc0);
            EMIT(fmaf(-2.f, d[1], s1), tA16, pxA16, k0 + nc1);
            EMIT(fmaf(-2.f, d[2], s2), tB16, pxB16, k0 + nc2);
            EMIT(fmaf(-2.f, d[3], s3), tB16, pxB16, k0 + nc3);
        }
    }
#undef EMIT
#undef MMA_TILE
#undef A_ADDR
    __syncthreads();

    // ---- epilogue: owner thread (pixel tid) exact-rescores ----
    u64v xp[32];
    float Sx = 0.f;
#pragma unroll
    for (int i = 0; i < 32; i++) {
        float a = lat[base + ((2 * i) << 12)];
        float c = lat[base + ((2 * i + 1) << 12)];
        float ta = a * a, tc = c * c;
        Sx = Sx + ta; Sx = Sx + tc;
        xp[i] = pack2(a, c);
    }

    float bestD = 3.4e38f;
    int bestK = 0;
    const int nc = cnt_sm[tid];
    if (*bad_sm || flag_sm[tid] || nc == 0 || nc > CAP) {
        for (int k = 0; k < KC; k++) {        // provably correct fallback
            float d = exact_dist(k, xp, Sx, emb, se_sm[k]);
            if (d < bestD || (d == bestD && k < bestK)) { bestD = d; bestK = k; }
        }
    } else {
        const int cbase = tid * CAP;
        bestK = KC - 1;
        for (int j = 0; j < nc; j++) {
            int k = cand_sm[cbase + j];
            float d = exact_dist(k, xp, Sx, emb, se_sm[k]);
            if (d < bestD || (d == bestD && k < bestK)) { bestD = d; bestK = k; }
        }
    }

    // q_st write + loss partial (exact R2 arithmetic)
    float lsum = 0.f;
    {
        const float4* qr = (const float4*)(emb + (bestK << 6));
#pragma unroll
        for (int j = 0; j < 16; j++) {
            float4 q = qr[j];
            float x0, x1, x2v, x3v;
            unpack2(xp[2 * j + 0], x0, x1);
            unpack2(xp[2 * j + 1], x2v, x3v);
            float e0 = q.x - x0, e1 = q.y - x1, e2 = q.z - x2v, e3 = q.w - x3v;
            out[base + ((4 * j + 0) << 12)] = x0 + e0;
            out[base + ((4 * j + 1) << 12)] = x1 + e1;
            out[base + ((4 * j + 2) << 12)] = x2v + e2;
            out[base + ((4 * j + 3) << 12)] = x3v + e3;
            lsum = fmaf(e0, e0, lsum); lsum = fmaf(e1, e1, lsum);
            lsum = fmaf(e2, e2, lsum); lsum = fmaf(e3, e3, lsum);
        }
    }
#pragma unroll
    for (int o = 16; o; o >>= 1) lsum += __shfl_xor_sync(0xffffffffu, lsum, o);
    if (lane == 0) red_sm[warp] = lsum;
    __syncthreads();
    if (tid == 0) {
        float t = 0.f;
#pragma unroll
        for (int w = 0; w < 8; w++) t += red_sm[w];
        g_partials[blockIdx.x] = t;
    }
}

__global__ void vq_reduce(float* __restrict__ out) {
    __shared__ float s[NCTAS];
    const int t = threadIdx.x;
    s[t] = g_partials[t];
    __syncthreads();
#pragma unroll
    for (int o = NCTAS / 2; o; o >>= 1) {
        if (t < o) s[t] += s[t + o];
        __syncthreads();
    }
    if (t == 0) {
        float m = s[0] * (1.0f / 8388608.0f);
        out[TENSOR_ELEMS] = 1.25f * m;
    }
}

extern "C" void kernel_launch(void* const* d_in, const int* in_sizes, int n_in,
                              void* d_out, int out_size) {
    const float* lat = (const float*)d_in[0];
    const float* emb = (const float*)d_in[1];
    float* out = (float*)d_out;

    cudaFuncSetAttribute(vq_main, cudaFuncAttributeMaxDynamicSharedMemorySize, SMEM_TOTAL);

    vq_prep<<<1, KC>>>(emb);
    vq_main<<<NCTAS, TPB, SMEM_TOTAL>>>(lat, emb, out);
    vq_reduce<<<1, NCTAS>>>(out);
}

// round 11
// speedup vs baseline: 2.0019x; 2.0019x over previous
#include <cuda_runtime.h>
#include <cuda_bf16.h>
#include <cstdint>

// VectorQuantizer: bf16 mma.sync prefilter with self-calibrating fragment
// mapping + exact-fp32 FFMA2 rescore. (tcgen05 unavailable on compute_103.)
//
// R10 fix: swizzled ldmatrix address for B ksteps 2-3 must apply the SW128
// XOR AFTER adding the +64 column offset ((off+64)^x != (off^x)+64 when the
// XOR'd col bits carry into the row field). This bug corrupted half the
// lanes' kstep-2/3 B rows in R5-R7 and tripped probe 2 in R9 (-> global
// fallback, 707us). Probes retained as the correctness safety net.

#define KC   512
#define DD   64
#define TENSOR_ELEMS 8388608
#define NCTAS 512            // 131072 px / 256
#define TPB   256
#define CAP   16

// smem layout (bytes)
#define OFF_A     0          // 256 rows x 128B bf16 (SW128)
#define OFF_CB    32768      // 512 rows x 128B bf16 (SW128)
#define OFF_SE    98304      // 512 f32
#define OFF_MARG  100352     // 256 f32
#define OFF_CNT   101376     // 256 i32
#define OFF_CAND  102400     // 256*CAP u16 = 8192 B
#define OFF_FLAG  110592     // 256 B
#define OFF_BAD   110848     // 4 B
#define OFF_RED   110880     // 8 f32
#define SMEM_TOTAL 110912

typedef unsigned long long u64v;

// ---------- packed fp32 helpers (frozen R2 formula) ----------
__device__ __forceinline__ u64v fma2(u64v a, u64v b, u64v c) {
    u64v d_; asm("fma.rn.f32x2 %0, %1, %2, %3;" : "=l"(d_) : "l"(a), "l"(b), "l"(c)); return d_;
}
__device__ __forceinline__ u64v add2(u64v a, u64v b) {
    u64v d_; asm("add.rn.f32x2 %0, %1, %2;" : "=l"(d_) : "l"(a), "l"(b)); return d_;
}
__device__ __forceinline__ u64v pack2(float lo, float hi) {
    u64v d_; asm("mov.b64 %0, {%1, %2};" : "=l"(d_) : "f"(lo), "f"(hi)); return d_;
}
__device__ __forceinline__ void unpack2(u64v v, float& lo, float& hi) {
    asm("mov.b64 {%0, %1}, %2;" : "=f"(lo), "=f"(hi) : "l"(v));
}

// ---------- mma / ldmatrix ----------
__device__ __forceinline__ void ldsm_x4(uint32_t addr, uint32_t& r0, uint32_t& r1,
                                        uint32_t& r2, uint32_t& r3) {
    asm volatile("ldmatrix.sync.aligned.m8n8.x4.shared.b16 {%0,%1,%2,%3}, [%4];"
                 : "=r"(r0), "=r"(r1), "=r"(r2), "=r"(r3) : "r"(addr));
}
__device__ __forceinline__ void mma_bf16(float* c,
                                         const uint32_t* a, uint32_t b0, uint32_t b1) {
    asm volatile("mma.sync.aligned.m16n8k16.row.col.f32.bf16.bf16.f32 "
                 "{%0,%1,%2,%3}, {%4,%5,%6,%7}, {%8,%9}, {%0,%1,%2,%3};"
                 : "+f"(c[0]), "+f"(c[1]), "+f"(c[2]), "+f"(c[3])
                 : "r"(a[0]), "r"(a[1]), "r"(a[2]), "r"(a[3]), "r"(b0), "r"(b1));
}
__device__ __forceinline__ uint32_t smem_u32(const void* p) {
    uint32_t a; asm("{ .reg .u64 t; cvta.to.shared.u64 t, %1; cvt.u32.u64 %0, t; }"
                    : "=r"(a) : "l"(p));
    return a;
}
static __device__ __forceinline__ uint32_t sw128(uint32_t off) {
    return off ^ ((off >> 3) & 0x70);
}

// ---------- device globals ----------
__device__ __nv_bfloat16 g_cb_bf16[KC * DD];
__device__ float g_se[KC];
__device__ float g_enorm_max;
__device__ float g_partials[NCTAS];

__global__ void vq_prep(const float* __restrict__ emb) {
    __shared__ float sm[KC];
    const int k = threadIdx.x;
    const float* r = emb + k * DD;
    float s = 0.f;
#pragma unroll
    for (int d = 0; d < DD; d++) {
        float v = r[d];
        float t = v * v;
        s = s + t;
        g_cb_bf16[k * DD + d] = __float2bfloat16(v);
    }
    g_se[k] = s;
    sm[k] = s;
    __syncthreads();
    for (int o = 256; o; o >>= 1) {
        if (k < o) sm[k] = fmaxf(sm[k], sm[k + o]);
        __syncthreads();
    }
    if (k == 0) g_enorm_max = sqrtf(sm[0]);
}

__device__ __forceinline__ float exact_dist(int k, const u64v* xp, float Sx,
                                            const float* __restrict__ emb, float sek) {
    const float4* er = (const float4*)(emb + (k << 6));
    u64v a0 = 0ull, a1 = 0ull, a2 = 0ull, a3 = 0ull;
#pragma unroll
    for (int j = 0; j < 8; j++) {
        float4 e0 = er[2 * j];
        float4 e1 = er[2 * j + 1];
        a0 = fma2(xp[4 * j + 0], pack2(e0.x, e0.y), a0);
        a1 = fma2(xp[4 * j + 1], pack2(e0.z, e0.w), a1);
        a2 = fma2(xp[4 * j + 2], pack2(e1.x, e1.y), a2);
        a3 = fma2(xp[4 * j + 3], pack2(e1.z, e1.w), a3);
    }
    u64v s2 = add2(add2(a0, a1), add2(a2, a3));
    float lo, hi; unpack2(s2, lo, hi);
    float dot = lo + hi;
    return fmaf(-2.f, dot, Sx + sek);
}

__device__ __forceinline__ int dec_pow2(float v, int& r, int& n) {
    uint32_t u = __float_as_uint(v);
    if (!(v > 0.f) || (u & 0x7FFFFFu)) return 1;
    int e = (int)(u >> 23) - 127;
    if (e < 0 || e > 127) return 1;
    r = e & 15;
    n = e >> 4;
    return (n > 7) ? 1 : 0;
}

__global__ void __launch_bounds__(TPB, 2)
vq_main(const float* __restrict__ lat, const float* __restrict__ emb, float* __restrict__ out) {
    extern __shared__ char smem[];
    const uint32_t sbase = smem_u32(smem);
    const int tid  = threadIdx.x;
    const int lane = tid & 31;
    const int warp = tid >> 5;

    float* se_sm   = (float*)(smem + OFF_SE);
    float* marg_sm = (float*)(smem + OFF_MARG);
    int*   cnt_sm  = (int*)(smem + OFF_CNT);
    unsigned short* cand_sm = (unsigned short*)(smem + OFF_CAND);
    unsigned char*  flag_sm = (unsigned char*)(smem + OFF_FLAG);
    int*   bad_sm  = (int*)(smem + OFF_BAD);
    float* red_sm  = (float*)(smem + OFF_RED);

    cnt_sm[tid] = 0;
    flag_sm[tid] = 0;
    if (tid == 0) *bad_sm = 0;

    const uint32_t axor = (uint32_t)(lane & 7) << 4;
    const int arow = warp * 32 + (lane & 15);
#define A_ADDR(T, ks) (sbase + OFF_A + \
    (((uint32_t)(arow + (T) * 16) * 128u + (uint32_t)(ks) * 32u + (uint32_t)(lane >> 4) * 16u) ^ axor))
    // B addresses: XOR applied to the COMPLETE column offset (R10 fix: the +64
    // for ksteps 2-3 must be inside the XOR, else it carries into the row bits).
    const uint32_t bcol = ((uint32_t)(lane & 7) * 128u) + (uint32_t)(lane >> 3) * 16u;
    const uint32_t baddr_lo = sbase + OFF_CB + (bcol ^ axor);          // ksteps 0,1
    const uint32_t baddr_hi = sbase + OFF_CB + ((bcol + 64u) ^ axor);  // ksteps 2,3

    int bad = 0;
    int rA = 0, rB = 0, nc0 = 0, nc1 = 1, nc2 = 0, nc3 = 1;

    // ================= PROBE 1: (row, col) mapping =================
    {
        const uint4 z = make_uint4(0, 0, 0, 0);
        uint4 f = z; f.x = (uint32_t)((127 + (tid & 15)) << 7);  // bf16 2^(tid&15) at d=0
#pragma unroll
        for (int j = 0; j < 8; j++)
            *(uint4*)(smem + OFF_A + sw128((uint32_t)tid * 128u + j * 16u)) = (j == 0) ? f : z;
        if (tid < 8) {
            uint4 fb = z; fb.x = (uint32_t)((127 + 16 * tid) << 7);  // bf16 2^(16n)
#pragma unroll
            for (int j = 0; j < 8; j++)
                *(uint4*)(smem + OFF_CB + sw128((uint32_t)tid * 128u + j * 16u)) = (j == 0) ? fb : z;
        }
    }
    __syncthreads();
    {
        uint32_t p[4], q[4], b00, b01, b10x, b11x;
        ldsm_x4(A_ADDR(0, 0), p[0], p[1], p[2], p[3]);
        ldsm_x4(A_ADDR(1, 0), q[0], q[1], q[2], q[3]);
        ldsm_x4(baddr_lo, b00, b01, b10x, b11x);
        float c[4] = {0.f, 0.f, 0.f, 0.f}, d[4] = {0.f, 0.f, 0.f, 0.f};
        mma_bf16(c, p, b00, b01);
        mma_bf16(d, q, b00, b01);
        int r0, r1, r2, r3;
        bad |= dec_pow2(c[0], r0, nc0);
        bad |= dec_pow2(c[1], r1, nc1);
        bad |= dec_pow2(c[2], r2, nc2);
        bad |= dec_pow2(c[3], r3, nc3);
        if (r0 != r1 || r2 != r3) bad = 1;
        rA = r0; rB = r2;
#pragma unroll
        for (int i = 0; i < 4; i++)
            if (__float_as_uint(d[i]) != __float_as_uint(c[i])) bad = 1;
    }
    __syncthreads();

    // ================= PROBE 2: kstep pairing =================
    {
        const uint4 z = make_uint4(0, 0, 0, 0);
#pragma unroll
        for (int j = 0; j < 8; j++) {
            uint4 w = z;
            if ((j & 1) == 0) w.x = (uint32_t)((127 + (j >> 1)) << 7);  // 2^ks at d=ks*16
            *(uint4*)(smem + OFF_A + sw128((uint32_t)tid * 128u + j * 16u)) = w;
        }
        if (tid < 8) {
#pragma unroll
            for (int j = 0; j < 8; j++) {
                uint4 w = z;
                if ((j & 1) == 0) w.x = (uint32_t)((127 + (j >> 1)) << 7);
                *(uint4*)(smem + OFF_CB + sw128((uint32_t)tid * 128u + j * 16u)) = w;
            }
        }
    }
    __syncthreads();
    {
        uint32_t a0[4], a1[4], a2[4], a3[4], b00, b01, b10, b11, b20, b21, b30, b31;
        ldsm_x4(A_ADDR(0, 0), a0[0], a0[1], a0[2], a0[3]);
        ldsm_x4(A_ADDR(0, 1), a1[0], a1[1], a1[2], a1[3]);
        ldsm_x4(A_ADDR(0, 2), a2[0], a2[1], a2[2], a2[3]);
        ldsm_x4(A_ADDR(0, 3), a3[0], a3[1], a3[2], a3[3]);
        ldsm_x4(baddr_lo, b00, b01, b10, b11);
        ldsm_x4(baddr_hi, b20, b21, b30, b31);
        float c[4] = {0.f, 0.f, 0.f, 0.f};
        mma_bf16(c, a0, b00, b01);
        mma_bf16(c, a1, b10, b11);
        mma_bf16(c, a2, b20, b21);
        mma_bf16(c, a3, b30, b31);
#pragma unroll
        for (int i = 0; i < 4; i++) if (c[i] != 85.0f) bad = 1;  // identity pairing only
    }
    if (bad) *bad_sm = 1;
    __syncthreads();

    // ================= stage real data =================
    const int P    = blockIdx.x * TPB + tid;
    const int base = ((P >> 12) << 18) + (P & 4095);
    {
        float Sx = 0.f;
        uint32_t xb[32];
#pragma unroll
        for (int i = 0; i < 32; i++) {
            float a = lat[base + ((2 * i) << 12)];
            float c = lat[base + ((2 * i + 1) << 12)];
            float ta = a * a, tc = c * c;
            Sx = Sx + ta; Sx = Sx + tc;
            __nv_bfloat162 h = __floats2bfloat162_rn(a, c);
            xb[i] = *(uint32_t*)&h;
        }
#pragma unroll
        for (int j = 0; j < 8; j++)
            *(uint4*)(smem + OFF_A + sw128((uint32_t)tid * 128u + j * 16u)) =
                make_uint4(xb[4 * j], xb[4 * j + 1], xb[4 * j + 2], xb[4 * j + 3]);
        marg_sm[tid] = 0.03125f * sqrtf(Sx) * 1.001f * g_enorm_max + 1e-4f;
    }
    {
        const uint4* cbg = (const uint4*)g_cb_bf16;
        for (int c = tid; c < 4096; c += TPB)
            *(uint4*)(smem + OFF_CB + sw128((uint32_t)c * 16u)) = cbg[c];
        for (int k = tid; k < KC; k += TPB) se_sm[k] = g_se[k];
    }
    __syncthreads();

    // ---- A fragments for real data ----
    uint32_t afr[2][4][4];
#pragma unroll
    for (int T = 0; T < 2; T++)
#pragma unroll
        for (int ks = 0; ks < 4; ks++)
            ldsm_x4(A_ADDR(T, ks), afr[T][ks][0], afr[T][ks][1], afr[T][ks][2], afr[T][ks][3]);

    // measured pixel routing
    const int pxA   = warp * 32 + rA;
    const int pxB   = warp * 32 + rB;
    const int pxA16 = pxA + 16;
    const int pxB16 = pxB + 16;

#define MMA_TILE(c, d, b00, b01, b10, b11, b20, b21, b30, b31) \
    mma_bf16(c, afr[0][0], b00, b01); mma_bf16(c, afr[0][1], b10, b11);  \
    mma_bf16(c, afr[0][2], b20, b21); mma_bf16(c, afr[0][3], b30, b31);  \
    mma_bf16(d, afr[1][0], b00, b01); mma_bf16(d, afr[1][1], b10, b11);  \
    mma_bf16(d, afr[1][2], b20, b21); mma_bf16(d, afr[1][3], b30, b31)

    // ---- pass 1: lane-local min approx score per pixel slot ----
    float tA = 3.4e38f, tB = 3.4e38f, tA16 = 3.4e38f, tB16 = 3.4e38f;
    for (int nt = 0; nt < 64; nt++) {
        uint32_t b00, b01, b10, b11, b20, b21, b30, b31;
        ldsm_x4(baddr_lo + (uint32_t)nt * 1024u, b00, b01, b10, b11);
        ldsm_x4(baddr_hi + (uint32_t)nt * 1024u, b20, b21, b30, b31);
        float c[4] = {0.f, 0.f, 0.f, 0.f}, d[4] = {0.f, 0.f, 0.f, 0.f};
        MMA_TILE(c, d, b00, b01, b10, b11, b20, b21, b30, b31);
        const int k0 = nt * 8;
        float s0 = se_sm[k0 + nc0], s1 = se_sm[k0 + nc1];
        float s2 = se_sm[k0 + nc2], s3 = se_sm[k0 + nc3];
        tA   = fminf(tA,   fminf(fmaf(-2.f, c[0], s0), fmaf(-2.f, c[1], s1)));
        tB   = fminf(tB,   fminf(fmaf(-2.f, c[2], s2), fmaf(-2.f, c[3], s3)));
        tA16 = fminf(tA16, fminf(fmaf(-2.f, d[0], s0), fmaf(-2.f, d[1], s1)));
        tB16 = fminf(tB16, fminf(fmaf(-2.f, d[2], s2), fmaf(-2.f, d[3], s3)));
    }
    tA   += marg_sm[pxA];
    tB   += marg_sm[pxB];
    tA16 += marg_sm[pxA16];
    tB16 += marg_sm[pxB16];

    // ---- pass 2: emit candidates (atomic per-pixel lists) ----
#define EMIT(score, thr, px, kk)                                          \
    do {                                                                  \
        if ((score) <= (thr)) {                                           \
            int _i = atomicAdd(&cnt_sm[px], 1);                           \
            if (_i < CAP) cand_sm[(px) * CAP + _i] = (unsigned short)(kk); \
            else flag_sm[px] = 1;                                         \
        }                                                                 \
    } while (0)
    for (int nt = 0; nt < 64; nt++) {
        uint32_t b00, b01, b10, b11, b20, b21, b30, b31;
        ldsm_x4(baddr_lo + (uint32_t)nt * 1024u, b00, b01, b10, b11);
        ldsm_x4(baddr_hi + (uint32_t)nt * 1024u, b20, b21, b30, b31);
        float c[4] = {0.f, 0.f, 0.f, 0.f}, d[4] = {0.f, 0.f, 0.f, 0.f};
        MMA_TILE(c, d, b00, b01, b10, b11, b20, b21, b30, b31);
        const int k0 = nt * 8;
        float s0 = se_sm[k0 + nc0], s1 = se_sm[k0 + nc1];
        float s2 = se_sm[k0 + nc2], s3 = se_sm[k0 + nc3];
        EMIT(fmaf(-2.f, c[0], s0), tA,   pxA,   k0 + nc0);
        EMIT(fmaf(-2.f, c[1], s1), tA,   pxA,   k0 + nc1);
        EMIT(fmaf(-2.f, c[2], s2), tB,   pxB,   k0 + nc2);
        EMIT(fmaf(-2.f, c[3], s3), tB,   pxB,   k0 + nc3);
        EMIT(fmaf(-2.f, d[0], s0), tA16, pxA16, k0 + nc0);
        EMIT(fmaf(-2.f, d[1], s1), tA16, pxA16, k0 + nc1);
        EMIT(fmaf(-2.f, d[2], s2), tB16, pxB16, k0 + nc2);
        EMIT(fmaf(-2.f, d[3], s3), tB16, pxB16, k0 + nc3);
    }
#undef EMIT
#undef MMA_TILE
#undef A_ADDR
    __syncthreads();

    // ---- epilogue: owner thread (pixel tid) exact-rescores ----
    u64v xp[32];
    float Sx = 0.f;
#pragma unroll
    for (int i = 0; i < 32; i++) {
        float a = lat[base + ((2 * i) << 12)];
        float c = lat[base + ((2 * i + 1) << 12)];
        float ta = a * a, tc = c * c;
        Sx = Sx + ta; Sx = Sx + tc;
        xp[i] = pack2(a, c);
    }

    float bestD = 3.4e38f;
    int bestK = 0;
    const int nc = cnt_sm[tid];
    if (*bad_sm || flag_sm[tid] || nc == 0 || nc > CAP) {
        for (int k = 0; k < KC; k++) {        // provably correct fallback
            float d = exact_dist(k, xp, Sx, emb, se_sm[k]);
            if (d < bestD || (d == bestD && k < bestK)) { bestD = d; bestK = k; }
        }
    } else {
        const int cbase = tid * CAP;
        bestK = KC - 1;
        for (int j = 0; j < nc; j++) {
            int k = cand_sm[cbase + j];
            float d = exact_dist(k, xp, Sx, emb, se_sm[k]);
            if (d < bestD || (d == bestD && k < bestK)) { bestD = d; bestK = k; }
        }
    }

    // q_st write + loss partial (exact R2 arithmetic)
    float lsum = 0.f;
    {
        const float4* qr = (const float4*)(emb + (bestK << 6));
#pragma unroll
        for (int j = 0; j < 16; j++) {
            float4 q = qr[j];
            float x0, x1, x2v, x3v;
            unpack2(xp[2 * j + 0], x0, x1);
            unpack2(xp[2 * j + 1], x2v, x3v);
            float e0 = q.x - x0, e1 = q.y - x1, e2 = q.z - x2v, e3 = q.w - x3v;
            out[base + ((4 * j + 0) << 12)] = x0 + e0;
            out[base + ((4 * j + 1) << 12)] = x1 + e1;
            out[base + ((4 * j + 2) << 12)] = x2v + e2;
            out[base + ((4 * j + 3) << 12)] = x3v + e3;
            lsum = fmaf(e0, e0, lsum); lsum = fmaf(e1, e1, lsum);
            lsum = fmaf(e2, e2, lsum); lsum = fmaf(e3, e3, lsum);
        }
    }
#pragma unroll
    for (int o = 16; o; o >>= 1) lsum += __shfl_xor_sync(0xffffffffu, lsum, o);
    if (lane == 0) red_sm[warp] = lsum;
    __syncthreads();
    if (tid == 0) {
        float t = 0.f;
#pragma unroll
        for (int w = 0; w < 8; w++) t += red_sm[w];
        g_partials[blockIdx.x] = t;
    }
}

__global__ void vq_reduce(float* __restrict__ out) {
    __shared__ float s[NCTAS];
    const int t = threadIdx.x;
    s[t] = g_partials[t];
    __syncthreads();
#pragma unroll
    for (int o = NCTAS / 2; o; o >>= 1) {
        if (t < o) s[t] += s[t + o];
        __syncthreads();
    }
    if (t == 0) {
        float m = s[0] * (1.0f / 8388608.0f);
        out[TENSOR_ELEMS] = 1.25f * m;
    }
}

extern "C" void kernel_launch(void* const* d_in, const int* in_sizes, int n_in,
                              void* d_out, int out_size) {
    const float* lat = (const float*)d_in[0];
    const float* emb = (const float*)d_in[1];
    float* out = (float*)d_out;

    cudaFuncSetAttribute(vq_main, cudaFuncAttributeMaxDynamicSharedMemorySize, SMEM_TOTAL);

    vq_prep<<<1, KC>>>(emb);
    vq_main<<<NCTAS, TPB, SMEM_TOTAL>>>(lat, emb, out);
    vq_reduce<<<1, NCTAS>>>(out);
}